// round 2
// baseline (speedup 1.0000x reference)
#include <cuda_runtime.h>
#include <cuda_bf16.h>

#define Bc    64
#define Tc    1000
#define Fc    512
#define Hc    8
#define KDc   32
#define NCc   8
#define CHUNK 125           // Tc / NCc
#define SCALE 0.17677669529663689f   // 1/sqrt(32)
#define NEGBIG (-3.4e38f)

// ---------------- device scratch (no allocation allowed) ----------------
__device__ float g_qh[Hc * KDc];            // q @ Wq + bq (unscaled)
__device__ float g_wk[Hc][Fc];              // scale * (Wk @ qh), per head
__device__ float g_cb[Hc];                  // scale * (qh . bk)
__device__ float g_m[Bc][NCc][Hc];
__device__ float g_l[Bc][NCc][Hc];
__device__ float g_acc[Bc][NCc][Hc][Fc];    // 8.4 MB un-normalized weighted x sums
__device__ float g_pooled[Bc][Fc];

// ---------------- packed fp32x2 FMA (FFMA2) ----------------
__device__ __forceinline__ float2 fma2(float2 d, float2 a, float2 b) {
    unsigned long long dd, aa, bb;
    dd = *reinterpret_cast<unsigned long long*>(&d);
    aa = *reinterpret_cast<unsigned long long*>(&a);
    bb = *reinterpret_cast<unsigned long long*>(&b);
    asm("fma.rn.f32x2 %0, %1, %2, %0;" : "+l"(dd) : "l"(aa), "l"(bb));
    return *reinterpret_cast<float2*>(&dd);
}

// ---------------- prep1: qh = q @ Wq + bq ----------------
__global__ __launch_bounds__(256) void prep1_kernel(const float* __restrict__ q,
                                                    const float* __restrict__ Wq,
                                                    const float* __restrict__ bq) {
    __shared__ float qs[Fc];
    __shared__ float4 part[4][64];
    int tid = threadIdx.x;
    qs[tid] = q[tid];
    qs[tid + 256] = q[tid + 256];
    __syncthreads();

    int oq = tid & 63;          // float4 index over the 256 (h,k) outputs
    int fc = tid >> 6;          // f chunk 0..3 (128 f each)
    const float4* Wq4 = reinterpret_cast<const float4*>(Wq);
    float4 p = make_float4(0.f, 0.f, 0.f, 0.f);
#pragma unroll 8
    for (int ff = 0; ff < 128; ff++) {
        int f = fc * 128 + ff;
        float qv = qs[f];
        float4 wv = Wq4[f * 64 + oq];
        p.x = fmaf(qv, wv.x, p.x);
        p.y = fmaf(qv, wv.y, p.y);
        p.z = fmaf(qv, wv.z, p.z);
        p.w = fmaf(qv, wv.w, p.w);
    }
    part[fc][oq] = p;
    __syncthreads();
    if (tid < 64) {
        float4 s = part[0][tid];
        for (int c = 1; c < 4; c++) {
            float4 t = part[c][tid];
            s.x += t.x; s.y += t.y; s.z += t.z; s.w += t.w;
        }
        float4 bb = reinterpret_cast<const float4*>(bq)[tid];
        s.x += bb.x; s.y += bb.y; s.z += bb.z; s.w += bb.w;
        reinterpret_cast<float4*>(g_qh)[tid] = s;
    }
}

// ---------------- prep2: wk_eff[h][f] = scale * sum_k Wk[f,h,k]*qh[h,k] ----------------
__global__ __launch_bounds__(256) void prep2_kernel(const float* __restrict__ Wk,
                                                    const float* __restrict__ bk) {
    __shared__ float4 qs4[64];
    int tid = threadIdx.x;
    if (tid < 64) qs4[tid] = reinterpret_cast<const float4*>(g_qh)[tid];
    __syncthreads();
    const float4* Wk4 = reinterpret_cast<const float4*>(Wk);
#pragma unroll
    for (int i = 0; i < 2; i++) {
        int o = blockIdx.x * 512 + i * 256 + tid;   // h = blockIdx.x, f = i*256+tid
        int h = o >> 9, f = o & 511;
        float s = 0.f;
#pragma unroll
        for (int k4 = 0; k4 < 8; k4++) {
            float4 wv = Wk4[f * 64 + h * 8 + k4];
            float4 qv = qs4[h * 8 + k4];
            s += wv.x * qv.x + wv.y * qv.y + wv.z * qv.z + wv.w * qv.w;
        }
        g_wk[h][f] = s * SCALE;
    }
    if (blockIdx.x == 0 && tid < 8) {
        float s = 0.f;
        for (int k = 0; k < 32; k++) s += bk[tid * 32 + k] * g_qh[tid * 32 + k];
        g_cb[tid] = s * SCALE;
    }
}

// ---------------- main: scores + chunk softmax + weighted pooling of x ----------------
__global__ __launch_bounds__(256, 2) void main_kernel(const float* __restrict__ x) {
    __shared__ __align__(16) float sc[CHUNK][8];   // scores, then p (exp)
    const int tid = threadIdx.x;
    const int w = tid >> 5, lane = tid & 31;
    const int b = blockIdx.y, c = blockIdx.x;
    const int t0 = c * CHUNK;

    // ---- pass 1: scores. warps 0-3 -> heads 0-3, warps 4-7 -> heads 4-7.
    const int hb = (w < 4) ? 0 : 4;
    const int r0 = w & 3;
    float2 wk2[4][8];                 // wk for this lane's 16 f, 4 heads (packed pairs)
#pragma unroll
    for (int hh = 0; hh < 4; hh++)
#pragma unroll
        for (int j = 0; j < 4; j++) {
            float4 wv = *reinterpret_cast<const float4*>(&g_wk[hb + hh][128 * j + 4 * lane]);
            wk2[hh][2 * j]     = make_float2(wv.x, wv.y);
            wk2[hh][2 * j + 1] = make_float2(wv.z, wv.w);
        }
    float cbl[4];
#pragma unroll
    for (int hh = 0; hh < 4; hh++) cbl[hh] = g_cb[hb + hh];

    for (int r = r0; r < CHUNK; r += 4) {
        const float4* xr = reinterpret_cast<const float4*>(
            x + ((size_t)b * Tc + t0 + r) * Fc) + lane;
        float4 xv[4];
#pragma unroll
        for (int j = 0; j < 4; j++) xv[j] = xr[32 * j];   // f = 4*lane + 128*j
        float2 part[4];
#pragma unroll
        for (int hh = 0; hh < 4; hh++) part[hh] = make_float2(0.f, 0.f);
#pragma unroll
        for (int hh = 0; hh < 4; hh++)
#pragma unroll
            for (int j = 0; j < 4; j++) {
                part[hh] = fma2(part[hh], make_float2(xv[j].x, xv[j].y), wk2[hh][2 * j]);
                part[hh] = fma2(part[hh], make_float2(xv[j].z, xv[j].w), wk2[hh][2 * j + 1]);
            }
#pragma unroll
        for (int hh = 0; hh < 4; hh++) {
            float s = part[hh].x + part[hh].y;
#pragma unroll
            for (int off = 16; off; off >>= 1) s += __shfl_xor_sync(0xffffffffu, s, off);
            if (lane == 0) sc[r][hb + hh] = s + cbl[hh];
        }
    }
    __syncthreads();

    // ---- pass 2: chunk-local softmax partials. warp w handles head h=w.
    {
        const int h = w;
        float vals[4];
        float mc = NEGBIG;
#pragma unroll
        for (int i = 0; i < 4; i++) {
            int t = lane + 32 * i;
            vals[i] = (t < CHUNK) ? sc[t][h] : NEGBIG;
            mc = fmaxf(mc, vals[i]);
        }
#pragma unroll
        for (int off = 16; off; off >>= 1) mc = fmaxf(mc, __shfl_xor_sync(0xffffffffu, mc, off));
        float ls = 0.f;
#pragma unroll
        for (int i = 0; i < 4; i++) {
            int t = lane + 32 * i;
            if (t < CHUNK) {
                float p = __expf(vals[i] - mc);
                sc[t][h] = p;
                ls += p;
            }
        }
#pragma unroll
        for (int off = 16; off; off >>= 1) ls += __shfl_xor_sync(0xffffffffu, ls, off);
        if (lane == 0) { g_m[b][c][w] = mc; g_l[b][c][w] = ls; }
    }
    __syncthreads();

    // ---- pass 3: acc[h][f] = sum_t p[t][h]*x[t][f]. thread owns f-pair, all 8 heads.
    float2 acc[8];
#pragma unroll
    for (int h = 0; h < 8; h++) acc[h] = make_float2(0.f, 0.f);
    const float2* xb = reinterpret_cast<const float2*>(
        x + ((size_t)b * Tc + t0) * Fc) + tid;   // f = 2*tid
#pragma unroll 5
    for (int t = 0; t < CHUNK; t++) {
        float2 xv = xb[t * (Fc / 2)];
        float4 p0 = *reinterpret_cast<const float4*>(&sc[t][0]);
        float4 p1 = *reinterpret_cast<const float4*>(&sc[t][4]);
        acc[0] = fma2(acc[0], xv, make_float2(p0.x, p0.x));
        acc[1] = fma2(acc[1], xv, make_float2(p0.y, p0.y));
        acc[2] = fma2(acc[2], xv, make_float2(p0.z, p0.z));
        acc[3] = fma2(acc[3], xv, make_float2(p0.w, p0.w));
        acc[4] = fma2(acc[4], xv, make_float2(p1.x, p1.x));
        acc[5] = fma2(acc[5], xv, make_float2(p1.y, p1.y));
        acc[6] = fma2(acc[6], xv, make_float2(p1.z, p1.z));
        acc[7] = fma2(acc[7], xv, make_float2(p1.w, p1.w));
    }
#pragma unroll
    for (int h = 0; h < 8; h++)
        *reinterpret_cast<float2*>(&g_acc[b][c][h][2 * tid]) = acc[h];
}

// ---------------- tail A: combine chunks -> xa -> ctx(Wv,bv) -> pooled(Wo,bo) ----------------
__global__ __launch_bounds__(256) void tail_a_kernel(const float* __restrict__ Wv,
                                                     const float* __restrict__ bv,
                                                     const float* __restrict__ Wo,
                                                     const float* __restrict__ bo) {
    __shared__ float xa[2][Hc][Fc];    // 32 KB
    __shared__ float ctxs[2][Hc * KDc];
    __shared__ float ew[2][NCc][Hc];
    __shared__ float invL[2][Hc];
    const int b0 = blockIdx.x * 2;
    const int tid = threadIdx.x;

    if (tid < 16) {
        int rb = tid >> 3, h = tid & 7, b = b0 + rb;
        float M = NEGBIG;
        for (int c = 0; c < NCc; c++) M = fmaxf(M, g_m[b][c][h]);
        float L = 0.f;
        for (int c = 0; c < NCc; c++) {
            float e = __expf(g_m[b][c][h] - M);
            ew[rb][c][h] = e;
            L += g_l[b][c][h] * e;
        }
        invL[rb][h] = 1.0f / L;
    }
    __syncthreads();

    // xa[rb][h][f] = (sum_c acc*e_c) / L : 8192 outputs
#pragma unroll
    for (int i = 0; i < 32; i++) {
        int o = tid + 256 * i;
        int rb = o >> 12, h = (o >> 9) & 7, f = o & 511, b = b0 + rb;
        float s = 0.f;
#pragma unroll
        for (int c = 0; c < NCc; c++) s += g_acc[b][c][h][f] * ew[rb][c][h];
        xa[rb][h][f] = s * invL[rb][h];
    }
    __syncthreads();

    // ctx[h][k] = sum_f xa[h][f] * Wv[f,h,k] + bv   (thread = (h,k), warp = one head)
    {
        const int h = tid >> 5;
        float s0 = bv[tid], s1 = bv[tid];
        for (int f = 0; f < 512; f++) {
            float wv = Wv[f * 256 + tid];
            s0 = fmaf(xa[0][h][f], wv, s0);
            s1 = fmaf(xa[1][h][f], wv, s1);
        }
        ctxs[0][tid] = s0;
        ctxs[1][tid] = s1;
    }
    __syncthreads();

    // pooled[f] = sum_hk ctx[hk]*Wo[hk,f] + bo[f]
    {
        float a00 = 0.f, a01 = 0.f, a10 = 0.f, a11 = 0.f;
        for (int hk = 0; hk < 256; hk++) {
            float w0 = Wo[hk * 512 + tid];
            float w1 = Wo[hk * 512 + tid + 256];
            float c0 = ctxs[0][hk], c1 = ctxs[1][hk];
            a00 = fmaf(c0, w0, a00);
            a01 = fmaf(c0, w1, a01);
            a10 = fmaf(c1, w0, a10);
            a11 = fmaf(c1, w1, a11);
        }
        g_pooled[b0][tid]           = a00 + bo[tid];
        g_pooled[b0][tid + 256]     = a01 + bo[tid + 256];
        g_pooled[b0 + 1][tid]       = a10 + bo[tid];
        g_pooled[b0 + 1][tid + 256] = a11 + bo[tid + 256];
    }
}

// ---------------- tail B: out = LayerNorm(pooled @ Wd) * gamma + beta ----------------
__global__ __launch_bounds__(256) void tail_b_kernel(const float* __restrict__ Wd,
                                                     const float* __restrict__ gamma,
                                                     const float* __restrict__ beta,
                                                     float* __restrict__ out) {
    __shared__ float ps[4][Fc];
    __shared__ float rs[8], rs2[8], stats[2];
    const int b0 = blockIdx.x * 4;
    const int tid = threadIdx.x, w = tid >> 5, lane = tid & 31;

    for (int i = tid; i < 4 * Fc; i += 256)
        ps[i >> 9][i & 511] = g_pooled[b0 + (i >> 9)][i & 511];
    __syncthreads();

    float a[4][2];
#pragma unroll
    for (int rb = 0; rb < 4; rb++) { a[rb][0] = 0.f; a[rb][1] = 0.f; }
    for (int f = 0; f < 512; f++) {
        float w0 = Wd[f * 512 + tid];
        float w1 = Wd[f * 512 + tid + 256];
#pragma unroll
        for (int rb = 0; rb < 4; rb++) {
            float pv = ps[rb][f];
            a[rb][0] = fmaf(pv, w0, a[rb][0]);
            a[rb][1] = fmaf(pv, w1, a[rb][1]);
        }
    }
#pragma unroll
    for (int rb = 0; rb < 4; rb++) {
        float v0 = a[rb][0], v1 = a[rb][1];
        float s = v0 + v1, s2 = v0 * v0 + v1 * v1;
#pragma unroll
        for (int off = 16; off; off >>= 1) {
            s  += __shfl_xor_sync(0xffffffffu, s, off);
            s2 += __shfl_xor_sync(0xffffffffu, s2, off);
        }
        if (lane == 0) { rs[w] = s; rs2[w] = s2; }
        __syncthreads();
        if (tid == 0) {
            float ts = 0.f, ts2 = 0.f;
            for (int i = 0; i < 8; i++) { ts += rs[i]; ts2 += rs2[i]; }
            float mu = ts * (1.0f / 512.0f);
            float var = ts2 * (1.0f / 512.0f) - mu * mu;
            stats[0] = mu;
            stats[1] = rsqrtf(var + 1e-6f);
        }
        __syncthreads();
        float mu = stats[0], rstd = stats[1];
        out[(b0 + rb) * 512 + tid]       = (v0 - mu) * rstd * gamma[tid] + beta[tid];
        out[(b0 + rb) * 512 + tid + 256] = (v1 - mu) * rstd * gamma[tid + 256] + beta[tid + 256];
        __syncthreads();
    }
}

// ---------------- launch ----------------
extern "C" void kernel_launch(void* const* d_in, const int* in_sizes, int n_in,
                              void* d_out, int out_size) {
    const float* x     = (const float*)d_in[0];
    const float* q     = (const float*)d_in[1];
    const float* Wq    = (const float*)d_in[2];
    const float* bq    = (const float*)d_in[3];
    const float* Wk    = (const float*)d_in[4];
    const float* bk    = (const float*)d_in[5];
    const float* Wv    = (const float*)d_in[6];
    const float* bv    = (const float*)d_in[7];
    const float* Wo    = (const float*)d_in[8];
    const float* bo    = (const float*)d_in[9];
    const float* Wd    = (const float*)d_in[10];
    const float* gamma = (const float*)d_in[11];
    const float* beta  = (const float*)d_in[12];
    float* out = (float*)d_out;

    prep1_kernel<<<1, 256>>>(q, Wq, bq);
    prep2_kernel<<<8, 256>>>(Wk, bk);
    main_kernel<<<dim3(NCc, Bc), 256>>>(x);
    tail_a_kernel<<<Bc / 2, 256>>>(Wv, bv, Wo, bo);
    tail_b_kernel<<<Bc / 4, 256>>>(Wd, gamma, beta, out);
}

// round 4
// speedup vs baseline: 1.6597x; 1.6597x over previous
#include <cuda_runtime.h>
#include <cuda_bf16.h>

#define Bc    64
#define Tc    1000
#define Fc    512
#define Hc    8
#define KDc   32
#define NCc   8
#define CHUNK 125           // Tc / NCc
#define SCALE 0.17677669529663689f   // 1/sqrt(32)
#define NEGBIG (-3.4e38f)

// ---------------- device scratch (no allocation allowed) ----------------
__device__ float g_qpart[32][Hc * KDc];     // per-block partial qh sums
__device__ float g_wk[Hc][Fc];              // scale * (Wk @ qh), per head
__device__ float g_cb[Hc];                  // scale * (qh . bk)
__device__ float g_m[Bc][NCc][Hc];
__device__ float g_l[Bc][NCc][Hc];
__device__ float g_acc[Bc][NCc][Hc][Fc];    // 8.4 MB un-normalized weighted x sums

// ---------------- packed fp32x2 FMA (FFMA2) ----------------
__device__ __forceinline__ float2 fma2(float2 d, float2 a, float2 b) {
    unsigned long long dd, aa, bb;
    dd = *reinterpret_cast<unsigned long long*>(&d);
    aa = *reinterpret_cast<unsigned long long*>(&a);
    bb = *reinterpret_cast<unsigned long long*>(&b);
    asm("fma.rn.f32x2 %0, %1, %2, %0;" : "+l"(dd) : "l"(aa), "l"(bb));
    return *reinterpret_cast<float2*>(&dd);
}

// ---------------- prep1: partial qh sums, 32 blocks over f-chunks ----------------
__global__ __launch_bounds__(256) void prep1_kernel(const float* __restrict__ q,
                                                    const float* __restrict__ Wq) {
    const int tid = threadIdx.x;
    const int f0 = blockIdx.x * 16;
    float qv[16];
#pragma unroll
    for (int ff = 0; ff < 16; ff++) qv[ff] = q[f0 + ff];
    float s = 0.f;
#pragma unroll
    for (int ff = 0; ff < 16; ff++)
        s = fmaf(qv[ff], Wq[(f0 + ff) * 256 + tid], s);
    g_qpart[blockIdx.x][tid] = s;
}

// ---------------- prep2: wk_eff[h][f] = scale * sum_k Wk[f,h,k]*qh[h,k] ----------------
__global__ __launch_bounds__(256) void prep2_kernel(const float* __restrict__ Wk,
                                                    const float* __restrict__ bk,
                                                    const float* __restrict__ bq) {
    __shared__ float qh[Hc * KDc];
    const int tid = threadIdx.x;
    {
        float s = bq[tid];
#pragma unroll
        for (int i = 0; i < 32; i++) s += g_qpart[i][tid];
        qh[tid] = s;
    }
    __syncthreads();

    const int f0 = blockIdx.x * 8;
    const int o = tid >> 2;          // 0..63 : (frow, h)
    const int sub = tid & 3;         // k-quarter
    const int f = f0 + (o >> 3);
    const int h = o & 7;
    const float4* Wk4 = reinterpret_cast<const float4*>(Wk);
    float4 w0 = Wk4[f * 64 + h * 8 + sub * 2];
    float4 w1 = Wk4[f * 64 + h * 8 + sub * 2 + 1];
    const float* qp = &qh[h * 32 + sub * 8];
    float s = w0.x * qp[0] + w0.y * qp[1] + w0.z * qp[2] + w0.w * qp[3]
            + w1.x * qp[4] + w1.y * qp[5] + w1.z * qp[6] + w1.w * qp[7];
    s += __shfl_xor_sync(0xffffffffu, s, 1);
    s += __shfl_xor_sync(0xffffffffu, s, 2);
    if (sub == 0) g_wk[h][f] = s * SCALE;

    if (blockIdx.x == 0 && tid < 8) {
        float c = 0.f;
        for (int k = 0; k < 32; k++) c += bk[tid * 32 + k] * qh[tid * 32 + k];
        g_cb[tid] = c * SCALE;
    }
}

// ---------------- main: scores + chunk softmax + weighted pooling of x ----------------
__global__ __launch_bounds__(256, 2) void main_kernel(const float* __restrict__ x) {
    __shared__ __align__(16) float sc[CHUNK][8];   // scores, then p (exp)
    const int tid = threadIdx.x;
    const int w = tid >> 5, lane = tid & 31;
    const int b = blockIdx.y, c = blockIdx.x;
    const int t0 = c * CHUNK;

    // ---- pass 1: scores. warps 0-3 -> heads 0-3, warps 4-7 -> heads 4-7.
    const int hb = (w < 4) ? 0 : 4;
    const int r0 = w & 3;
    float2 wk2[4][8];                 // wk for this lane's 16 f, 4 heads (packed pairs)
#pragma unroll
    for (int hh = 0; hh < 4; hh++)
#pragma unroll
        for (int j = 0; j < 4; j++) {
            float4 wv = *reinterpret_cast<const float4*>(&g_wk[hb + hh][128 * j + 4 * lane]);
            wk2[hh][2 * j]     = make_float2(wv.x, wv.y);
            wk2[hh][2 * j + 1] = make_float2(wv.z, wv.w);
        }
    float cbl[4];
#pragma unroll
    for (int hh = 0; hh < 4; hh++) cbl[hh] = g_cb[hb + hh];

    for (int r = r0; r < CHUNK; r += 4) {
        const float4* xr = reinterpret_cast<const float4*>(
            x + ((size_t)b * Tc + t0 + r) * Fc) + lane;
        float4 xv[4];
#pragma unroll
        for (int j = 0; j < 4; j++) xv[j] = xr[32 * j];   // f = 4*lane + 128*j
        float2 part[4];
#pragma unroll
        for (int hh = 0; hh < 4; hh++) part[hh] = make_float2(0.f, 0.f);
#pragma unroll
        for (int hh = 0; hh < 4; hh++)
#pragma unroll
            for (int j = 0; j < 4; j++) {
                part[hh] = fma2(part[hh], make_float2(xv[j].x, xv[j].y), wk2[hh][2 * j]);
                part[hh] = fma2(part[hh], make_float2(xv[j].z, xv[j].w), wk2[hh][2 * j + 1]);
            }
#pragma unroll
        for (int hh = 0; hh < 4; hh++) {
            float s = part[hh].x + part[hh].y;
#pragma unroll
            for (int off = 16; off; off >>= 1) s += __shfl_xor_sync(0xffffffffu, s, off);
            if (lane == 0) sc[r][hb + hh] = s + cbl[hh];
        }
    }
    __syncthreads();

    // ---- pass 2: chunk-local softmax partials. warp w handles head h=w.
    {
        const int h = w;
        float vals[4];
        float mc = NEGBIG;
#pragma unroll
        for (int i = 0; i < 4; i++) {
            int t = lane + 32 * i;
            vals[i] = (t < CHUNK) ? sc[t][h] : NEGBIG;
            mc = fmaxf(mc, vals[i]);
        }
#pragma unroll
        for (int off = 16; off; off >>= 1) mc = fmaxf(mc, __shfl_xor_sync(0xffffffffu, mc, off));
        float ls = 0.f;
#pragma unroll
        for (int i = 0; i < 4; i++) {
            int t = lane + 32 * i;
            if (t < CHUNK) {
                float p = __expf(vals[i] - mc);
                sc[t][h] = p;
                ls += p;
            }
        }
#pragma unroll
        for (int off = 16; off; off >>= 1) ls += __shfl_xor_sync(0xffffffffu, ls, off);
        if (lane == 0) { g_m[b][c][w] = mc; g_l[b][c][w] = ls; }
    }
    __syncthreads();

    // ---- pass 3: acc[h][f] = sum_t p[t][h]*x[t][f]. thread owns f-pair, all 8 heads.
    float2 acc[8];
#pragma unroll
    for (int h = 0; h < 8; h++) acc[h] = make_float2(0.f, 0.f);
    const float2* xb = reinterpret_cast<const float2*>(
        x + ((size_t)b * Tc + t0) * Fc) + tid;   // f = 2*tid
#pragma unroll 5
    for (int t = 0; t < CHUNK; t++) {
        float2 xv = xb[t * (Fc / 2)];
        float4 p0 = *reinterpret_cast<const float4*>(&sc[t][0]);
        float4 p1 = *reinterpret_cast<const float4*>(&sc[t][4]);
        acc[0] = fma2(acc[0], xv, make_float2(p0.x, p0.x));
        acc[1] = fma2(acc[1], xv, make_float2(p0.y, p0.y));
        acc[2] = fma2(acc[2], xv, make_float2(p0.z, p0.z));
        acc[3] = fma2(acc[3], xv, make_float2(p0.w, p0.w));
        acc[4] = fma2(acc[4], xv, make_float2(p1.x, p1.x));
        acc[5] = fma2(acc[5], xv, make_float2(p1.y, p1.y));
        acc[6] = fma2(acc[6], xv, make_float2(p1.z, p1.z));
        acc[7] = fma2(acc[7], xv, make_float2(p1.w, p1.w));
    }
#pragma unroll
    for (int h = 0; h < 8; h++)
        *reinterpret_cast<float2*>(&g_acc[b][c][h][2 * tid]) = acc[h];
}

// ---------------- fused tail: combine -> ctx(Wv,bv) -> pooled(Wo,bo) -> Wd -> LN ----------------
__global__ __launch_bounds__(512) void tail_kernel(const float* __restrict__ Wv,
                                                   const float* __restrict__ bv,
                                                   const float* __restrict__ Wo,
                                                   const float* __restrict__ bo,
                                                   const float* __restrict__ Wd,
                                                   const float* __restrict__ gamma,
                                                   const float* __restrict__ beta,
                                                   float* __restrict__ out) {
    __shared__ float xs[Hc][Fc];        // 16 KB: normalized attention-pooled x
    __shared__ float ew[NCc][Hc];
    __shared__ float invL[Hc];
    __shared__ float ctx_part[2][Hc * KDc];
    __shared__ float ctxs[Hc * KDc];
    __shared__ float pooled[Fc];
    __shared__ float red[32];
    __shared__ float stats[2];
    const int b = blockIdx.x;
    const int tid = threadIdx.x;

    if (tid < 8) {
        float M = NEGBIG;
#pragma unroll
        for (int c = 0; c < NCc; c++) M = fmaxf(M, g_m[b][c][tid]);
        float L = 0.f;
#pragma unroll
        for (int c = 0; c < NCc; c++) {
            float e = __expf(g_m[b][c][tid] - M);
            ew[c][tid] = e;
            L += g_l[b][c][tid] * e;
        }
        invL[tid] = 1.0f / L;
    }
    __syncthreads();

    // combine chunks: xs[h][f] = (sum_c acc*e_c)/L
#pragma unroll
    for (int i = 0; i < 8; i++) {
        int o = tid + 512 * i;
        int h = o >> 9, f = o & 511;
        float s = 0.f;
#pragma unroll
        for (int c = 0; c < NCc; c++) s = fmaf(g_acc[b][c][h][f], ew[c][h], s);
        xs[h][f] = s * invL[h];
    }
    __syncthreads();

    // ctx[h][k] = sum_f xs[h][f] * Wv[f,h,k]  (2 threads per output, split f)
    {
        const int o = tid & 255, half = tid >> 8, h = o >> 5;
        const float* wp = Wv + (half * 256) * 256 + o;
        const float* xp = &xs[h][half * 256];
        float s0 = 0.f, s1 = 0.f;
#pragma unroll 8
        for (int f = 0; f < 256; f += 2) {
            s0 = fmaf(xp[f], wp[f * 256], s0);
            s1 = fmaf(xp[f + 1], wp[(f + 1) * 256], s1);
        }
        ctx_part[half][o] = s0 + s1;
    }
    __syncthreads();
    if (tid < 256) ctxs[tid] = ctx_part[0][tid] + ctx_part[1][tid] + bv[tid];
    __syncthreads();

    // pooled[f] = sum_hk ctx[hk]*Wo[hk,f] + bo[f]
    {
        const float* wp = Wo + tid;
        float s0 = 0.f, s1 = 0.f;
#pragma unroll 8
        for (int hk = 0; hk < 256; hk += 2) {
            s0 = fmaf(ctxs[hk], wp[hk * 512], s0);
            s1 = fmaf(ctxs[hk + 1], wp[(hk + 1) * 512], s1);
        }
        pooled[tid] = s0 + s1 + bo[tid];
    }
    __syncthreads();

    // dense: v = pooled . Wd[:, tid], then LayerNorm across the block
    float v;
    {
        const float* wp = Wd + tid;
        float s0 = 0.f, s1 = 0.f, s2 = 0.f, s3 = 0.f;
#pragma unroll 4
        for (int f = 0; f < 512; f += 4) {
            s0 = fmaf(pooled[f],     wp[f * 512],       s0);
            s1 = fmaf(pooled[f + 1], wp[(f + 1) * 512], s1);
            s2 = fmaf(pooled[f + 2], wp[(f + 2) * 512], s2);
            s3 = fmaf(pooled[f + 3], wp[(f + 3) * 512], s3);
        }
        v = (s0 + s1) + (s2 + s3);
    }
    float s = v, s2 = v * v;
#pragma unroll
    for (int off = 16; off; off >>= 1) {
        s  += __shfl_xor_sync(0xffffffffu, s, off);
        s2 += __shfl_xor_sync(0xffffffffu, s2, off);
    }
    const int w = tid >> 5, lane = tid & 31;
    if (lane == 0) { red[w] = s; red[16 + w] = s2; }
    __syncthreads();
    if (tid == 0) {
        float ts = 0.f, ts2 = 0.f;
#pragma unroll
        for (int i = 0; i < 16; i++) { ts += red[i]; ts2 += red[16 + i]; }
        float mu = ts * (1.0f / 512.0f);
        float var = ts2 * (1.0f / 512.0f) - mu * mu;
        stats[0] = mu;
        stats[1] = rsqrtf(var + 1e-6f);
    }
    __syncthreads();
    out[b * 512 + tid] = (v - stats[0]) * stats[1] * gamma[tid] + beta[tid];
}

// ---------------- launch ----------------
extern "C" void kernel_launch(void* const* d_in, const int* in_sizes, int n_in,
                              void* d_out, int out_size) {
    const float* x     = (const float*)d_in[0];
    const float* q     = (const float*)d_in[1];
    const float* Wq    = (const float*)d_in[2];
    const float* bq    = (const float*)d_in[3];
    const float* Wk    = (const float*)d_in[4];
    const float* bk    = (const float*)d_in[5];
    const float* Wv    = (const float*)d_in[6];
    const float* bv    = (const float*)d_in[7];
    const float* Wo    = (const float*)d_in[8];
    const float* bo    = (const float*)d_in[9];
    const float* Wd    = (const float*)d_in[10];
    const float* gamma = (const float*)d_in[11];
    const float* beta  = (const float*)d_in[12];
    float* out = (float*)d_out;

    prep1_kernel<<<32, 256>>>(q, Wq);
    prep2_kernel<<<64, 256>>>(Wk, bk, bq);
    main_kernel<<<dim3(NCc, Bc), 256>>>(x);
    tail_kernel<<<Bc, 512>>>(Wv, bv, Wo, bo, Wd, gamma, beta, out);
}

// round 6
// speedup vs baseline: 1.8537x; 1.1169x over previous
#include <cuda_runtime.h>
#include <cuda_bf16.h>

#define Bc    64
#define Tc    1000
#define Fc    512
#define Hc    8
#define KDc   32
#define NCc   8
#define CHUNK 125           // Tc / NCc
#define SCALE 0.17677669529663689f   // 1/sqrt(32)
#define NEGBIG (-3.4e38f)

// ---------------- device scratch (no allocation allowed) ----------------
__device__ float g_qpart[32][Hc * KDc];     // per-block partial qh sums
__device__ float g_wk[Hc][Fc];              // scale * (Wk @ qh), per head
__device__ float g_cb[Hc];                  // scale * (qh . bk)
__device__ float g_m[Bc][NCc][Hc];
__device__ float g_l[Bc][NCc][Hc];
__device__ float g_acc[Bc][NCc][Hc][Fc];    // 8.4 MB un-normalized weighted x sums
__device__ float g_ctx[Bc][Hc * KDc];
__device__ float g_pooled[Bc][Fc];

// ---------------- packed fp32x2 FMA (FFMA2) ----------------
__device__ __forceinline__ float2 fma2(float2 d, float2 a, float2 b) {
    unsigned long long dd, aa, bb;
    dd = *reinterpret_cast<unsigned long long*>(&d);
    aa = *reinterpret_cast<unsigned long long*>(&a);
    bb = *reinterpret_cast<unsigned long long*>(&b);
    asm("fma.rn.f32x2 %0, %1, %2, %0;" : "+l"(dd) : "l"(aa), "l"(bb));
    return *reinterpret_cast<float2*>(&dd);
}

// ---------------- prep1: partial qh sums, 32 blocks over f-chunks ----------------
__global__ __launch_bounds__(256) void prep1_kernel(const float* __restrict__ q,
                                                    const float* __restrict__ Wq) {
    const int tid = threadIdx.x;
    const int f0 = blockIdx.x * 16;
    float qv[16];
#pragma unroll
    for (int ff = 0; ff < 16; ff++) qv[ff] = q[f0 + ff];
    float s = 0.f;
#pragma unroll
    for (int ff = 0; ff < 16; ff++)
        s = fmaf(qv[ff], Wq[(f0 + ff) * 256 + tid], s);
    g_qpart[blockIdx.x][tid] = s;
}

// ---------------- prep2: wk_eff[h][f] = scale * sum_k Wk[f,h,k]*qh[h,k] ----------------
__global__ __launch_bounds__(256) void prep2_kernel(const float* __restrict__ Wk,
                                                    const float* __restrict__ bk,
                                                    const float* __restrict__ bq) {
    __shared__ float qh[Hc * KDc];
    const int tid = threadIdx.x;
    {
        float s = bq[tid];
#pragma unroll
        for (int i = 0; i < 32; i++) s += g_qpart[i][tid];
        qh[tid] = s;
    }
    __syncthreads();

    const int f0 = blockIdx.x * 8;
    const int o = tid >> 2;          // 0..63 : (frow, h)
    const int sub = tid & 3;         // k-quarter
    const int f = f0 + (o >> 3);
    const int h = o & 7;
    const float4* Wk4 = reinterpret_cast<const float4*>(Wk);
    float4 w0 = Wk4[f * 64 + h * 8 + sub * 2];
    float4 w1 = Wk4[f * 64 + h * 8 + sub * 2 + 1];
    const float* qp = &qh[h * 32 + sub * 8];
    float s = w0.x * qp[0] + w0.y * qp[1] + w0.z * qp[2] + w0.w * qp[3]
            + w1.x * qp[4] + w1.y * qp[5] + w1.z * qp[6] + w1.w * qp[7];
    s += __shfl_xor_sync(0xffffffffu, s, 1);
    s += __shfl_xor_sync(0xffffffffu, s, 2);
    if (sub == 0) g_wk[h][f] = s * SCALE;

    if (blockIdx.x == 0 && tid < 8) {
        float c = 0.f;
        for (int k = 0; k < 32; k++) c += bk[tid * 32 + k] * qh[tid * 32 + k];
        g_cb[tid] = c * SCALE;
    }
}

// ---------------- main: scores + chunk softmax + weighted pooling of x ----------------
__global__ __launch_bounds__(256, 2) void main_kernel(const float* __restrict__ x) {
    __shared__ __align__(16) float sc[CHUNK][8];   // scores, then p (exp)
    const int tid = threadIdx.x;
    const int w = tid >> 5, lane = tid & 31;
    const int b = blockIdx.y, c = blockIdx.x;
    const int t0 = c * CHUNK;

    // ---- pass 1: scores. warps 0-3 -> heads 0-3, warps 4-7 -> heads 4-7.
    const int hb = (w < 4) ? 0 : 4;
    const int r0 = w & 3;
    float2 wk2[4][8];                 // wk for this lane's 16 f, 4 heads (packed pairs)
#pragma unroll
    for (int hh = 0; hh < 4; hh++)
#pragma unroll
        for (int j = 0; j < 4; j++) {
            float4 wv = *reinterpret_cast<const float4*>(&g_wk[hb + hh][128 * j + 4 * lane]);
            wk2[hh][2 * j]     = make_float2(wv.x, wv.y);
            wk2[hh][2 * j + 1] = make_float2(wv.z, wv.w);
        }
    float cbl[4];
#pragma unroll
    for (int hh = 0; hh < 4; hh++) cbl[hh] = g_cb[hb + hh];

    for (int r = r0; r < CHUNK; r += 4) {
        const float4* xr = reinterpret_cast<const float4*>(
            x + ((size_t)b * Tc + t0 + r) * Fc) + lane;
        float4 xv[4];
#pragma unroll
        for (int j = 0; j < 4; j++) xv[j] = xr[32 * j];   // f = 4*lane + 128*j
        float2 part[4];
#pragma unroll
        for (int hh = 0; hh < 4; hh++) part[hh] = make_float2(0.f, 0.f);
#pragma unroll
        for (int hh = 0; hh < 4; hh++)
#pragma unroll
            for (int j = 0; j < 4; j++) {
                part[hh] = fma2(part[hh], make_float2(xv[j].x, xv[j].y), wk2[hh][2 * j]);
                part[hh] = fma2(part[hh], make_float2(xv[j].z, xv[j].w), wk2[hh][2 * j + 1]);
            }
#pragma unroll
        for (int hh = 0; hh < 4; hh++) {
            float s = part[hh].x + part[hh].y;
#pragma unroll
            for (int off = 16; off; off >>= 1) s += __shfl_xor_sync(0xffffffffu, s, off);
            if (lane == 0) sc[r][hb + hh] = s + cbl[hh];
        }
    }
    __syncthreads();

    // ---- pass 2: chunk-local softmax partials. warp w handles head h=w.
    {
        const int h = w;
        float vals[4];
        float mc = NEGBIG;
#pragma unroll
        for (int i = 0; i < 4; i++) {
            int t = lane + 32 * i;
            vals[i] = (t < CHUNK) ? sc[t][h] : NEGBIG;
            mc = fmaxf(mc, vals[i]);
        }
#pragma unroll
        for (int off = 16; off; off >>= 1) mc = fmaxf(mc, __shfl_xor_sync(0xffffffffu, mc, off));
        float ls = 0.f;
#pragma unroll
        for (int i = 0; i < 4; i++) {
            int t = lane + 32 * i;
            if (t < CHUNK) {
                float p = __expf(vals[i] - mc);
                sc[t][h] = p;
                ls += p;
            }
        }
#pragma unroll
        for (int off = 16; off; off >>= 1) ls += __shfl_xor_sync(0xffffffffu, ls, off);
        if (lane == 0) { g_m[b][c][w] = mc; g_l[b][c][w] = ls; }
    }
    __syncthreads();

    // ---- pass 3: acc[h][f] = sum_t p[t][h]*x[t][f]. thread owns f-pair, all 8 heads.
    float2 acc[8];
#pragma unroll
    for (int h = 0; h < 8; h++) acc[h] = make_float2(0.f, 0.f);
    const float2* xb = reinterpret_cast<const float2*>(
        x + ((size_t)b * Tc + t0) * Fc) + tid;   // f = 2*tid
#pragma unroll 5
    for (int t = 0; t < CHUNK; t++) {
        float2 xv = xb[t * (Fc / 2)];
        float4 p0 = *reinterpret_cast<const float4*>(&sc[t][0]);
        float4 p1 = *reinterpret_cast<const float4*>(&sc[t][4]);
        acc[0] = fma2(acc[0], xv, make_float2(p0.x, p0.x));
        acc[1] = fma2(acc[1], xv, make_float2(p0.y, p0.y));
        acc[2] = fma2(acc[2], xv, make_float2(p0.z, p0.z));
        acc[3] = fma2(acc[3], xv, make_float2(p0.w, p0.w));
        acc[4] = fma2(acc[4], xv, make_float2(p1.x, p1.x));
        acc[5] = fma2(acc[5], xv, make_float2(p1.y, p1.y));
        acc[6] = fma2(acc[6], xv, make_float2(p1.z, p1.z));
        acc[7] = fma2(acc[7], xv, make_float2(p1.w, p1.w));
    }
#pragma unroll
    for (int h = 0; h < 8; h++)
        *reinterpret_cast<float2*>(&g_acc[b][c][h][2 * tid]) = acc[h];
}

// ---------------- T1: per-(b,h) chunk combine + ctx = xa @ Wv[:,h,:] + bv ----------------
__global__ __launch_bounds__(128) void ctx_kernel(const float* __restrict__ Wv,
                                                  const float* __restrict__ bv) {
    __shared__ __align__(16) float xa[Fc];
    __shared__ float part[4][KDc];
    const int b = blockIdx.x >> 3;
    const int h = blockIdx.x & 7;
    const int tid = threadIdx.x;
    const int w = tid >> 5, lane = tid & 31;

    // softmax combine weights (computed redundantly per thread — no sync needed)
    float M = NEGBIG;
#pragma unroll
    for (int c = 0; c < NCc; c++) M = fmaxf(M, g_m[b][c][h]);
    float ew[NCc];
    float L = 0.f;
#pragma unroll
    for (int c = 0; c < NCc; c++) {
        float e = __expf(g_m[b][c][h] - M);
        ew[c] = e;
        L += g_l[b][c][h] * e;
    }
    const float invL = 1.0f / L;

    // combine chunks: xa[f] = (sum_c acc[c][f]*ew[c]) * invL  (float4 per thread)
    float4 a = make_float4(0.f, 0.f, 0.f, 0.f);
#pragma unroll
    for (int c = 0; c < NCc; c++) {
        float4 v = reinterpret_cast<const float4*>(&g_acc[b][c][h][0])[tid];
        a.x = fmaf(v.x, ew[c], a.x);
        a.y = fmaf(v.y, ew[c], a.y);
        a.z = fmaf(v.z, ew[c], a.z);
        a.w = fmaf(v.w, ew[c], a.w);
    }
    a.x *= invL; a.y *= invL; a.z *= invL; a.w *= invL;
    reinterpret_cast<float4*>(xa)[tid] = a;
    __syncthreads();

    // warp w covers f in [w*128,(w+1)*128), lane = k. Coalesced Wv loads.
    {
        const float* wvp = Wv + h * KDc + lane;
        const int f0 = w * 128;
        float s0 = 0.f, s1 = 0.f, s2 = 0.f, s3 = 0.f;
#pragma unroll 8
        for (int i = 0; i < 128; i += 4) {
            s0 = fmaf(xa[f0 + i],     wvp[(f0 + i) * 256],     s0);
            s1 = fmaf(xa[f0 + i + 1], wvp[(f0 + i + 1) * 256], s1);
            s2 = fmaf(xa[f0 + i + 2], wvp[(f0 + i + 2) * 256], s2);
            s3 = fmaf(xa[f0 + i + 3], wvp[(f0 + i + 3) * 256], s3);
        }
        part[w][lane] = (s0 + s1) + (s2 + s3);
    }
    __syncthreads();
    if (tid < KDc) {
        float r = part[0][tid] + part[1][tid] + part[2][tid] + part[3][tid]
                + bv[h * KDc + tid];
        g_ctx[b][h * KDc + tid] = r;
    }
}

// ---------------- T2: pooled[b][f] = ctx[b,:] @ Wo + bo ----------------
__global__ __launch_bounds__(512) void pooled_kernel(const float* __restrict__ Wo,
                                                     const float* __restrict__ bo) {
    __shared__ float cs[Hc * KDc];
    const int b = blockIdx.x;
    const int tid = threadIdx.x;
    if (tid < 256) cs[tid] = g_ctx[b][tid];
    __syncthreads();

    const float* wp = Wo + tid;
    float s0 = 0.f, s1 = 0.f, s2 = 0.f, s3 = 0.f;
#pragma unroll 8
    for (int hk = 0; hk < 256; hk += 4) {
        s0 = fmaf(cs[hk],     wp[hk * 512],       s0);
        s1 = fmaf(cs[hk + 1], wp[(hk + 1) * 512], s1);
        s2 = fmaf(cs[hk + 2], wp[(hk + 2) * 512], s2);
        s3 = fmaf(cs[hk + 3], wp[(hk + 3) * 512], s3);
    }
    g_pooled[b][tid] = (s0 + s1) + (s2 + s3) + bo[tid];
}

// ---------------- T3: out = LayerNorm(pooled @ Wd) * gamma + beta ----------------
__global__ __launch_bounds__(512) void dense_ln_kernel(const float* __restrict__ Wd,
                                                       const float* __restrict__ gamma,
                                                       const float* __restrict__ beta,
                                                       float* __restrict__ out) {
    __shared__ float ps[Fc];
    __shared__ float red[32];
    __shared__ float stats[2];
    const int b = blockIdx.x;
    const int tid = threadIdx.x;

    ps[tid] = g_pooled[b][tid];
    __syncthreads();

    float v;
    {
        const float* wp = Wd + tid;
        float s0 = 0.f, s1 = 0.f, s2 = 0.f, s3 = 0.f;
#pragma unroll 8
        for (int f = 0; f < 512; f += 4) {
            s0 = fmaf(ps[f],     wp[f * 512],       s0);
            s1 = fmaf(ps[f + 1], wp[(f + 1) * 512], s1);
            s2 = fmaf(ps[f + 2], wp[(f + 2) * 512], s2);
            s3 = fmaf(ps[f + 3], wp[(f + 3) * 512], s3);
        }
        v = (s0 + s1) + (s2 + s3);
    }
    float s = v, s2 = v * v;
#pragma unroll
    for (int off = 16; off; off >>= 1) {
        s  += __shfl_xor_sync(0xffffffffu, s, off);
        s2 += __shfl_xor_sync(0xffffffffu, s2, off);
    }
    const int w = tid >> 5, lane = tid & 31;
    if (lane == 0) { red[w] = s; red[16 + w] = s2; }
    __syncthreads();
    if (tid == 0) {
        float ts = 0.f, ts2 = 0.f;
#pragma unroll
        for (int i = 0; i < 16; i++) { ts += red[i]; ts2 += red[16 + i]; }
        float mu = ts * (1.0f / 512.0f);
        float var = ts2 * (1.0f / 512.0f) - mu * mu;
        stats[0] = mu;
        stats[1] = rsqrtf(var + 1e-6f);
    }
    __syncthreads();
    out[b * 512 + tid] = (v - stats[0]) * stats[1] * gamma[tid] + beta[tid];
}

// ---------------- launch ----------------
extern "C" void kernel_launch(void* const* d_in, const int* in_sizes, int n_in,
                              void* d_out, int out_size) {
    const float* x     = (const float*)d_in[0];
    const float* q     = (const float*)d_in[1];
    const float* Wq    = (const float*)d_in[2];
    const float* bq    = (const float*)d_in[3];
    const float* Wk    = (const float*)d_in[4];
    const float* bk    = (const float*)d_in[5];
    const float* Wv    = (const float*)d_in[6];
    const float* bv    = (const float*)d_in[7];
    const float* Wo    = (const float*)d_in[8];
    const float* bo    = (const float*)d_in[9];
    const float* Wd    = (const float*)d_in[10];
    const float* gamma = (const float*)d_in[11];
    const float* beta  = (const float*)d_in[12];
    float* out = (float*)d_out;

    prep1_kernel<<<32, 256>>>(q, Wq);
    prep2_kernel<<<64, 256>>>(Wk, bk, bq);
    main_kernel<<<dim3(NCc, Bc), 256>>>(x);
    ctx_kernel<<<Bc * Hc, 128>>>(Wv, bv);
    pooled_kernel<<<Bc, 512>>>(Wo, bo);
    dense_ln_kernel<<<Bc, 512>>>(Wd, gamma, beta, out);
}